// round 6
// baseline (speedup 1.0000x reference)
#include <cuda_runtime.h>
#include <cuda_fp16.h>
#include <cstdint>

// SimpleDistanceLoss:
//   search: S[m][n] = bsq[n] - 2<a_m,b_n> via fp8 e4m3 m16n8k32 mma.sync
//           (f32 accumulators; exact fp32 bsq folded into the C operand of the
//            first k-step; A pre-scaled by -2 before quantization).
//           Search tracks the winning candidate GROUP (tile, wn, lane-pair).
//   tail:   exact fp32 recompute over the 16 candidate columns of the winning
//           group (8 j-blocks x 2 parities); min is the row's NN distance.

#define NPTS   16384
#define DDIM   64
#define NTILES 128
#define NBLK   128

__device__ uint4 g_aunits[NBLK * 512];     // fp8 fragment units of -2*A (8KB/tile)
__device__ uint2 g_bunits[NTILES * 1024];  // fp8 fragment units of B (8KB/tile)
__device__ float g_bsqf[NPTS];             // exact fp32 ||b||^2
__device__ float g_bsum[NBLK];

// ---- smem byte offsets ----
#define SM_A     0
#define SM_B0    8192
#define SM_B1    16384
#define SM_BSQ0  24576                     // 512 B (128 f32)
#define SM_BSQ1  25088
#define SM_REDV  25600                     // float[128][2]
#define SM_REDM  26624                     // int[128][2]
#define SM_WS    27648                     // float[4]
#define SMEM_BYTES 27664

static __device__ __forceinline__ uint32_t smem_u32(const void* p) {
    uint32_t a;
    asm("{ .reg .u64 t; cvta.to.shared.u64 t, %1; cvt.u32.u64 %0, t; }" : "=r"(a) : "l"(p));
    return a;
}
#define CP16(sm, gp) \
    asm volatile("cp.async.cg.shared.global [%0], [%1], 16;" :: "r"(sm), "l"(gp))
#define CP_COMMIT() asm volatile("cp.async.commit_group;" ::: "memory")
#define CP_WAIT0()  asm volatile("cp.async.wait_group 0;" ::: "memory")

// fp8 e4m3 MMA, f32 accumulators.
static __device__ __forceinline__ void mma_f8_acc(float c[4], uint4 a, uint2 b) {
    asm("mma.sync.aligned.m16n8k32.row.col.f32.e4m3.e4m3.f32 "
        "{%0,%1,%2,%3},{%4,%5,%6,%7},{%8,%9},{%0,%1,%2,%3};"
        : "+f"(c[0]), "+f"(c[1]), "+f"(c[2]), "+f"(c[3])
        : "r"(a.x), "r"(a.y), "r"(a.z), "r"(a.w), "r"(b.x), "r"(b.y));
}
static __device__ __forceinline__ void mma_f8_init(float c[4], uint4 a, uint2 b,
                                                   float q0, float q1) {
    asm("mma.sync.aligned.m16n8k32.row.col.f32.e4m3.e4m3.f32 "
        "{%0,%1,%2,%3},{%4,%5,%6,%7},{%8,%9},{%10,%11,%10,%11};"
        : "=f"(c[0]), "=f"(c[1]), "=f"(c[2]), "=f"(c[3])
        : "r"(a.x), "r"(a.y), "r"(a.z), "r"(a.w), "r"(b.x), "r"(b.y),
          "f"(q0), "f"(q1));
}

static __device__ __forceinline__ uint32_t f32x4_to_e4m3x4(float4 v) {
    uint16_t lo, hi;
    asm("cvt.rn.satfinite.e4m3x2.f32 %0, %1, %2;" : "=h"(lo) : "f"(v.y), "f"(v.x));
    asm("cvt.rn.satfinite.e4m3x2.f32 %0, %1, %2;" : "=h"(hi) : "f"(v.w), "f"(v.z));
    return (uint32_t)lo | ((uint32_t)hi << 16);
}

// ---------------------------------------------------------------------------
// Prep: fp32 -> e4m3 (A scaled by -2), repack into k32 fragment-unit layout,
// compute exact fp32 bsq. Block b<128: A tile; b>=128: B tile b-128.
// A unit (ks, mb, lane), 16B: {X[r][kq..+3], X[r+8][kq..+3],
//                              X[r][kq+16..+19], X[r+8][kq+16..+19]}
//   with r = mb*16 + lane/4, kq = ks*32 + (lane%4)*4.
// B unit (ks, nb, lane), 8B:  {X[c][kq..+3], X[c][kq+16..+19]}
//   with c = nb*8 + lane/4.
// ---------------------------------------------------------------------------
__global__ __launch_bounds__(256)
void prep_kernel(const float* __restrict__ A, const float* __restrict__ B) {
    __shared__ uint8_t sh8[128 * 64];
    __shared__ float nr[256];
    const int tid = threadIdx.x;
    const bool isB = blockIdx.x >= NBLK;
    const int tile = blockIdx.x & (NBLK - 1);
    const float sc = isB ? 1.0f : -2.0f;

    const float4* s4 = reinterpret_cast<const float4*>(isB ? B : A) + (size_t)tile * 128 * 16;
    const int row = tid & 127, hf = tid >> 7;
    float nrm = 0.f;
    uint32_t pk[8];
#pragma unroll
    for (int i = 0; i < 8; i++) {
        float4 v = s4[row * 16 + hf * 8 + i];
        nrm += v.x * v.x + v.y * v.y + v.z * v.z + v.w * v.w;
        pk[i] = f32x4_to_e4m3x4(make_float4(sc * v.x, sc * v.y, sc * v.z, sc * v.w));
    }
    uint4* dsts = reinterpret_cast<uint4*>(&sh8[row * 64 + hf * 32]);
    dsts[0] = make_uint4(pk[0], pk[1], pk[2], pk[3]);
    dsts[1] = make_uint4(pk[4], pk[5], pk[6], pk[7]);
    nr[tid] = nrm;
    __syncthreads();
    if (isB && tid < 128) g_bsqf[tile * 128 + tid] = nr[tid] + nr[tid + 128];

    if (!isB) {
        uint4* dst = g_aunits + (size_t)tile * 512;
#pragma unroll
        for (int i = 0; i < 2; i++) {
            int u = tid + i * 256;
            int ks = u >> 8, mb = (u >> 5) & 7, lane = u & 31;
            int r = mb * 16 + (lane >> 2), k = ks * 32 + (lane & 3) * 4;
            uint4 v;
            v.x = *reinterpret_cast<const uint32_t*>(&sh8[r * 64 + k]);
            v.y = *reinterpret_cast<const uint32_t*>(&sh8[(r + 8) * 64 + k]);
            v.z = *reinterpret_cast<const uint32_t*>(&sh8[r * 64 + k + 16]);
            v.w = *reinterpret_cast<const uint32_t*>(&sh8[(r + 8) * 64 + k + 16]);
            dst[u] = v;
        }
    } else {
        uint2* dst = g_bunits + (size_t)tile * 1024;
#pragma unroll
        for (int i = 0; i < 4; i++) {
            int u = tid + i * 256;
            int ks = u >> 9, nb = (u >> 5) & 15, lane = u & 31;
            int c = nb * 8 + (lane >> 2), k = ks * 32 + (lane & 3) * 4;
            uint2 v;
            v.x = *reinterpret_cast<const uint32_t*>(&sh8[c * 64 + k]);
            v.y = *reinterpret_cast<const uint32_t*>(&sh8[c * 64 + k + 16]);
            dst[u] = v;
        }
    }
}

// ---------------------------------------------------------------------------
// Main: 128 CTAs x 256 threads, 8 compute warps (warp tile 32x64).
// ---------------------------------------------------------------------------
__global__ __launch_bounds__(256, 1)
void dist_kernel(const float* __restrict__ A, const float* __restrict__ B) {
    extern __shared__ char sm[];
    const uint32_t smb = smem_u32(sm);
    const int tid = threadIdx.x;
    const int wid = tid >> 5, lane = tid & 31;
    const int wm = wid & 3, wn = wid >> 2;     // rows wm*32, cols wn*64
    const int rowbase = blockIdx.x * 128;
    const int idxbase = wn * 64 + (lane & 3) * 2;

    // ---- prologue: A units + B tile 0 + bsq tile 0 ----
    {
        const uint4* gA = g_aunits + (size_t)blockIdx.x * 512;
        const uint4* gB = reinterpret_cast<const uint4*>(g_bunits);
#pragma unroll
        for (int i = 0; i < 2; i++) {
            int u = tid + i * 256;
            CP16(smb + SM_A + u * 16, gA + u);
            CP16(smb + SM_B0 + u * 16, gB + u);
        }
        if (tid < 32) CP16(smb + SM_BSQ0 + tid * 16, reinterpret_cast<const uint4*>(g_bsqf) + tid);
        CP_COMMIT();
        CP_WAIT0();
        __syncthreads();
    }

    const uint4* Au = reinterpret_cast<const uint4*>(sm + SM_A);
    float pmin[4];
    int ptile[4];
#pragma unroll
    for (int s = 0; s < 4; s++) { pmin[s] = 3.4e38f; ptile[s] = 0; }

    for (int t = 0; t < NTILES; t++) {
        if (t + 1 < NTILES) {
            const uint4* gB = reinterpret_cast<const uint4*>(g_bunits + (size_t)(t + 1) * 1024);
            const uint32_t dstB = smb + ((t & 1) ? SM_B0 : SM_B1);
#pragma unroll
            for (int i = 0; i < 2; i++) {
                int u = tid + i * 256;
                CP16(dstB + u * 16, gB + u);
            }
            if (tid < 32)
                CP16(smb + ((t & 1) ? SM_BSQ0 : SM_BSQ1) + tid * 16,
                     reinterpret_cast<const uint4*>(g_bsqf + (t + 1) * 128) + tid);
            CP_COMMIT();
        }

        const uint2* Bu = reinterpret_cast<const uint2*>(sm + ((t & 1) ? SM_B1 : SM_B0));
        const float* bsqs = reinterpret_cast<const float*>(sm + ((t & 1) ? SM_BSQ1 : SM_BSQ0));

        float2 bq[8];
#pragma unroll
        for (int j = 0; j < 8; j++)
            bq[j] = *reinterpret_cast<const float2*>(&bsqs[idxbase + j * 8]);

        float acc[2][8][4];
#pragma unroll
        for (int ks = 0; ks < 2; ks++) {
            uint4 af[2];
            uint2 bf[8];
#pragma unroll
            for (int mt = 0; mt < 2; mt++)
                af[mt] = Au[(ks * 8 + wm * 2 + mt) * 32 + lane];
#pragma unroll
            for (int j = 0; j < 8; j++)
                bf[j] = Bu[(ks * 16 + wn * 8 + j) * 32 + lane];
#pragma unroll
            for (int mt = 0; mt < 2; mt++)
#pragma unroll
                for (int j = 0; j < 8; j++) {
                    if (ks == 0) mma_f8_init(acc[mt][j], af[mt], bf[j], bq[j].x, bq[j].y);
                    else         mma_f8_acc(acc[mt][j], af[mt], bf[j]);
                }
        }

        // fold tile minimum per (mt, row-half) slot over 8 j-blocks x 2 cols
#pragma unroll
        for (int mt = 0; mt < 2; mt++)
#pragma unroll
            for (int rh = 0; rh < 2; rh++) {
                float v = fminf(acc[mt][0][rh * 2], acc[mt][0][rh * 2 + 1]);
#pragma unroll
                for (int j = 1; j < 8; j++)
                    v = fminf(v, fminf(acc[mt][j][rh * 2], acc[mt][j][rh * 2 + 1]));
                const int s = mt * 2 + rh;
                if (v < pmin[s]) { pmin[s] = v; ptile[s] = t; }
            }

        CP_WAIT0();
        __syncthreads();
    }

    // ---- per-row winner (group) across the 4 lane-pairs and wn halves ----
    float* redv = reinterpret_cast<float*>(sm + SM_REDV);
    int*   redm = reinterpret_cast<int*>(sm + SM_REDM);
#pragma unroll
    for (int s = 0; s < 4; s++) {
        float v = pmin[s];
        int meta = (ptile[s] << 3) | (wn << 2) | (lane & 3);
#pragma unroll
        for (int mk = 1; mk <= 2; mk <<= 1) {
            float ov = __shfl_xor_sync(0xffffffffu, v, mk);
            int om = __shfl_xor_sync(0xffffffffu, meta, mk);
            if (ov < v) { v = ov; meta = om; }
        }
        if ((lane & 3) == 0) {
            int row = wm * 32 + (s >> 1) * 16 + (s & 1) * 8 + (lane >> 2);
            redv[row * 2 + wn] = v;
            redm[row * 2 + wn] = meta;
        }
    }
    __syncthreads();

    // ---- exact fp32 recompute over the 16 candidate columns ----
    float* ws = reinterpret_cast<float*>(sm + SM_WS);
    if (tid < 128) {
        float v0 = redv[tid * 2 + 0], v1 = redv[tid * 2 + 1];
        int sel = (v1 < v0) ? 1 : 0;
        int meta = redm[tid * 2 + sel];
        int base = (meta >> 3) * 128 + ((meta >> 2) & 1) * 64 + (meta & 3) * 2;

        const float4* ar = reinterpret_cast<const float4*>(A) + (size_t)(rowbase + tid) * 16;
        float4 a4[16];
#pragma unroll
        for (int i = 0; i < 16; i++) a4[i] = ar[i];

        float best = 3.4e38f;
#pragma unroll
        for (int jj = 0; jj < 16; jj++) {
            int col = base + (jj >> 1) * 8 + (jj & 1);
            const float4* br = reinterpret_cast<const float4*>(B) + (size_t)col * 16;
            float s = 0.f;
#pragma unroll
            for (int i = 0; i < 16; i++) {
                float4 b4 = br[i];
                float dx = a4[i].x - b4.x, dy = a4[i].y - b4.y;
                float dz = a4[i].z - b4.z, dw = a4[i].w - b4.w;
                s += dx * dx + dy * dy + dz * dz + dw * dw;
            }
            best = fminf(best, s);
        }
#pragma unroll
        for (int mk = 16; mk; mk >>= 1) best += __shfl_xor_sync(0xffffffffu, best, mk);
        if (lane == 0) ws[wid] = best;
    }
    __syncthreads();
    if (tid == 0) g_bsum[blockIdx.x] = ws[0] + ws[1] + ws[2] + ws[3];
}

// ---------------------------------------------------------------------------
__global__ void final_reduce_kernel(float* __restrict__ out) {
    int lane = threadIdx.x;
    float v = 0.f;
#pragma unroll
    for (int i = 0; i < NBLK / 32; i++) v += g_bsum[lane + i * 32];
#pragma unroll
    for (int mk = 16; mk; mk >>= 1) v += __shfl_xor_sync(0xffffffffu, v, mk);
    if (lane == 0) out[0] = v;
}

extern "C" void kernel_launch(void* const* d_in, const int* in_sizes, int n_in,
                              void* d_out, int out_size) {
    const float* A = (const float*)d_in[0];
    const float* B = (const float*)d_in[1];
    float* out = (float*)d_out;

    cudaFuncSetAttribute(dist_kernel, cudaFuncAttributeMaxDynamicSharedMemorySize, SMEM_BYTES);

    prep_kernel<<<2 * NBLK, 256>>>(A, B);
    dist_kernel<<<NBLK, 256, SMEM_BYTES>>>(A, B);
    final_reduce_kernel<<<1, 32>>>(out);
}

// round 7
// speedup vs baseline: 1.0790x; 1.0790x over previous
#include <cuda_runtime.h>
#include <cuda_fp16.h>
#include <cstdint>

// SimpleDistanceLoss:
//   search: S[m][n] = bsq[n] - 2<a_m,b_n> via fp16 m16n8k16 mma.sync with fp16
//           accumulators (fastest legacy-pipe format on sm_103a, rt~12).
//           Persistent CTAs: 152 CTAs statically partition the 16384
//           (row-block, col-tile) quanta for near-perfect SM load balance.
//           Per-row winners merged via 64-bit atomicMin of (ordered-float-key,
//           meta) — deterministic (min is order-independent, meta rides along).
//   tail:   exact fp32 recompute over the 8 candidate columns of each row's
//           winning group.

#define NPTS   16384
#define DDIM   64
#define NRB    128              // row blocks of 128
#define NCT    128              // col tiles of 128
#define NQ     (NRB * NCT)      // 16384 quanta
#define NCTA   152              // persistent CTAs (GB300: 152 SMs)
#define NTAILB 64

__device__ uint4 g_aunits[NRB * 1024];     // fp16 fragment units of -2*A
__device__ uint4 g_bunits[NCT * 1024];     // fp16 fragment units of B
__device__ __align__(16) __half g_bsqh[NPTS];
__device__ unsigned long long g_rowkey[NPTS];   // (fkey(v)<<32) | meta
__device__ float g_bsum[NTAILB];

// ---- smem byte offsets ----
#define SM_A     0
#define SM_B0    16384
#define SM_B1    32768
#define SM_BSQ0  49152
#define SM_BSQ1  49408
#define SMEM_BYTES 49664

static __device__ __forceinline__ uint32_t smem_u32(const void* p) {
    uint32_t a;
    asm("{ .reg .u64 t; cvta.to.shared.u64 t, %1; cvt.u32.u64 %0, t; }" : "=r"(a) : "l"(p));
    return a;
}
#define CP16(sm, gp) \
    asm volatile("cp.async.cg.shared.global [%0], [%1], 16;" :: "r"(sm), "l"(gp))
#define CP_COMMIT() asm volatile("cp.async.commit_group;" ::: "memory")
#define CP_WAIT0()  asm volatile("cp.async.wait_group 0;" ::: "memory")

static __device__ __forceinline__ void mma_h_acc(uint32_t c[2], uint32_t a0, uint32_t a1,
                                                 uint32_t a2, uint32_t a3,
                                                 uint32_t b0, uint32_t b1) {
    asm("mma.sync.aligned.m16n8k16.row.col.f16.f16.f16.f16 "
        "{%0,%1},{%2,%3,%4,%5},{%6,%7},{%0,%1};"
        : "+r"(c[0]), "+r"(c[1])
        : "r"(a0), "r"(a1), "r"(a2), "r"(a3), "r"(b0), "r"(b1));
}
static __device__ __forceinline__ void mma_h_init(uint32_t c[2], uint32_t a0, uint32_t a1,
                                                  uint32_t a2, uint32_t a3,
                                                  uint32_t b0, uint32_t b1, uint32_t bq) {
    asm("mma.sync.aligned.m16n8k16.row.col.f16.f16.f16.f16 "
        "{%0,%1},{%2,%3,%4,%5},{%6,%7},{%8,%8};"
        : "=r"(c[0]), "=r"(c[1])
        : "r"(a0), "r"(a1), "r"(a2), "r"(a3), "r"(b0), "r"(b1), "r"(bq));
}

// order-preserving float -> uint key (works for negative values too)
static __device__ __forceinline__ unsigned fkey(float v) {
    unsigned u = __float_as_uint(v);
    return (u & 0x80000000u) ? ~u : (u | 0x80000000u);
}

// ---------------------------------------------------------------------------
// Prep: fp32 -> fp16 (A scaled by -2), repack to fragment-unit layout, bsq,
// and init g_rowkey. Block b<128: A tile b; b>=128: B tile b-128.
// ---------------------------------------------------------------------------
__global__ __launch_bounds__(256)
void prep_kernel(const float* __restrict__ A, const float* __restrict__ B) {
    __shared__ __half sh[128 * 64];
    __shared__ float nr[256];
    const int tid = threadIdx.x;
    const bool isB = blockIdx.x >= NRB;
    const int tile = blockIdx.x & (NRB - 1);
    const float sc = isB ? 1.0f : -2.0f;

    {   // rowkey init (first 64 blocks cover all rows)
        int gid = blockIdx.x * 256 + tid;
        if (gid < NPTS) g_rowkey[gid] = ~0ull;
    }

    const float4* s4 = reinterpret_cast<const float4*>(isB ? B : A) + (size_t)tile * 128 * 16;
    const int row = tid & 127, hf = tid >> 7;
    float nrm = 0.f;
    half2* sh2 = reinterpret_cast<half2*>(sh);
#pragma unroll
    for (int i = 0; i < 8; i++) {
        float4 v = s4[row * 16 + hf * 8 + i];
        nrm += v.x * v.x + v.y * v.y + v.z * v.z + v.w * v.w;
        sh2[row * 32 + hf * 16 + i * 2 + 0] = __floats2half2_rn(sc * v.x, sc * v.y);
        sh2[row * 32 + hf * 16 + i * 2 + 1] = __floats2half2_rn(sc * v.z, sc * v.w);
    }
    nr[tid] = nrm;
    __syncthreads();
    if (isB && tid < 128) g_bsqh[tile * 128 + tid] = __float2half_rn(nr[tid] + nr[tid + 128]);

    uint4* dst = (isB ? g_bunits : g_aunits) + (size_t)tile * 1024;
#pragma unroll
    for (int i = 0; i < 4; i++) {
        int u = tid + i * 256;
        int ks = u >> 8, blk = (u >> 5) & 7, s = u & 31;
        int x = blk * 16 + (s >> 2), k = ks * 16 + (s & 3) * 2;
        const uint32_t* p0 = reinterpret_cast<const uint32_t*>(&sh[x * 64 + k]);
        const uint32_t* p1 = reinterpret_cast<const uint32_t*>(&sh[(x + 8) * 64 + k]);
        uint4 v;
        v.x = p0[0]; v.y = p1[0]; v.z = p0[4]; v.w = p1[4];
        dst[u] = v;
    }
}

// ---------------------------------------------------------------------------
// Main: persistent CTAs over quanta q = rb*128 + ct.
// ---------------------------------------------------------------------------
__global__ __launch_bounds__(256, 1)
void dist_kernel() {
    extern __shared__ char sm[];
    const uint32_t smb = smem_u32(sm);
    const int tid = threadIdx.x;
    const int wid = tid >> 5, lane = tid & 31;
    const int wm = wid & 3, wn = wid >> 2;     // rows wm*32, cols wn*64
    const int idxbase = wn * 64 + (lane & 3) * 2;

    const int QS = (int)(((long long)blockIdx.x * NQ) / NCTA);
    const int QE = (int)(((long long)(blockIdx.x + 1) * NQ) / NCTA);

    float pmin[8];
    int ptile[8];
    int cur_rb = -1;

    // prologue: first B tile into stage 0
    {
        const int ct0 = QS & (NCT - 1);
        const uint4* gB = g_bunits + (size_t)ct0 * 1024;
#pragma unroll
        for (int i = 0; i < 4; i++) {
            int u = tid + i * 256;
            CP16(smb + SM_B0 + u * 16, gB + u);
        }
        if (tid < 16)
            CP16(smb + SM_BSQ0 + tid * 16,
                 reinterpret_cast<const uint4*>(g_bsqh + ct0 * 128) + tid);
        CP_COMMIT();
    }

    int li = 0;
    for (int q = QS; q < QE; q++, li++) {
        const int rb = q >> 7, ct = q & (NCT - 1), st = li & 1;

        if (rb != cur_rb) {
            // flush previous row-block's minima
            if (cur_rb >= 0) {
#pragma unroll
                for (int s = 0; s < 4; s++) {
                    float v0 = pmin[2 * s], v1 = pmin[2 * s + 1];
                    int h = (v1 < v0) ? 1 : 0;
                    float v = h ? v1 : v0;
                    int meta = (ptile[2 * s + h] << 4) | (wn << 3) | ((lane & 3) * 2 + h);
#pragma unroll
                    for (int mk = 1; mk <= 2; mk <<= 1) {
                        float ov = __shfl_xor_sync(0xffffffffu, v, mk);
                        int om = __shfl_xor_sync(0xffffffffu, meta, mk);
                        if (ov < v) { v = ov; meta = om; }
                    }
                    if ((lane & 3) == 0) {
                        int row = cur_rb * 128 + wm * 32 + (s >> 1) * 16 + (s & 1) * 8 + (lane >> 2);
                        atomicMin(&g_rowkey[row],
                                  ((unsigned long long)fkey(v) << 32) | (unsigned)meta);
                    }
                }
            }
#pragma unroll
            for (int s = 0; s < 8; s++) { pmin[s] = 3.4e38f; ptile[s] = 0; }

            // load A fragments for the new row block
            const uint4* gA = g_aunits + (size_t)rb * 1024;
#pragma unroll
            for (int i = 0; i < 4; i++) {
                int u = tid + i * 256;
                CP16(smb + SM_A + u * 16, gA + u);
            }
            CP_COMMIT();
            CP_WAIT0();
            __syncthreads();
            cur_rb = rb;
        }

        // prefetch next quantum's B tile into the other stage
        if (q + 1 < QE) {
            const int ctn = (q + 1) & (NCT - 1);
            const uint4* gB = g_bunits + (size_t)ctn * 1024;
            const uint32_t dstB = smb + (st ? SM_B0 : SM_B1);
#pragma unroll
            for (int i = 0; i < 4; i++) {
                int u = tid + i * 256;
                CP16(dstB + u * 16, gB + u);
            }
            if (tid < 16)
                CP16(smb + (st ? SM_BSQ0 : SM_BSQ1) + tid * 16,
                     reinterpret_cast<const uint4*>(g_bsqh + ctn * 128) + tid);
            CP_COMMIT();
        }

        const uint4* Au = reinterpret_cast<const uint4*>(sm + SM_A);
        const uint4* Bu = reinterpret_cast<const uint4*>(sm + (st ? SM_B1 : SM_B0));
        const char* bsqs = sm + (st ? SM_BSQ1 : SM_BSQ0);

        uint32_t bq[8];
#pragma unroll
        for (int j = 0; j < 8; j++)
            bq[j] = *reinterpret_cast<const uint32_t*>(bsqs + (idxbase + j * 8) * 2);

        uint32_t acc[2][8][2];
#pragma unroll
        for (int ks = 0; ks < 4; ks++) {
            uint4 af[2], bf[4];
#pragma unroll
            for (int mt = 0; mt < 2; mt++)
                af[mt] = Au[(ks * 8 + wm * 2 + mt) * 32 + lane];
#pragma unroll
            for (int p = 0; p < 4; p++)
                bf[p] = Bu[(ks * 8 + wn * 4 + p) * 32 + lane];
#pragma unroll
            for (int mt = 0; mt < 2; mt++)
#pragma unroll
                for (int p = 0; p < 4; p++) {
                    if (ks == 0) {
                        mma_h_init(acc[mt][2 * p],     af[mt].x, af[mt].y, af[mt].z, af[mt].w,
                                   bf[p].x, bf[p].z, bq[2 * p]);
                        mma_h_init(acc[mt][2 * p + 1], af[mt].x, af[mt].y, af[mt].z, af[mt].w,
                                   bf[p].y, bf[p].w, bq[2 * p + 1]);
                    } else {
                        mma_h_acc(acc[mt][2 * p],     af[mt].x, af[mt].y, af[mt].z, af[mt].w,
                                  bf[p].x, bf[p].z);
                        mma_h_acc(acc[mt][2 * p + 1], af[mt].x, af[mt].y, af[mt].z, af[mt].w,
                                  bf[p].y, bf[p].w);
                    }
                }
        }

        // fold tile minimum per (mt, row-half) slot across the 8 j-blocks
#pragma unroll
        for (int mt = 0; mt < 2; mt++)
#pragma unroll
            for (int rh = 0; rh < 2; rh++) {
                __half2 mn = *reinterpret_cast<__half2*>(&acc[mt][0][rh]);
#pragma unroll
                for (int j = 1; j < 8; j++)
                    mn = __hmin2(mn, *reinterpret_cast<__half2*>(&acc[mt][j][rh]));
                float2 f = __half22float2(mn);
                const int s = mt * 2 + rh;
                if (f.x < pmin[2 * s + 0]) { pmin[2 * s + 0] = f.x; ptile[2 * s + 0] = ct; }
                if (f.y < pmin[2 * s + 1]) { pmin[2 * s + 1] = f.y; ptile[2 * s + 1] = ct; }
            }

        CP_WAIT0();
        __syncthreads();
    }

    // final flush
    if (cur_rb >= 0) {
#pragma unroll
        for (int s = 0; s < 4; s++) {
            float v0 = pmin[2 * s], v1 = pmin[2 * s + 1];
            int h = (v1 < v0) ? 1 : 0;
            float v = h ? v1 : v0;
            int meta = (ptile[2 * s + h] << 4) | (wn << 3) | ((lane & 3) * 2 + h);
#pragma unroll
            for (int mk = 1; mk <= 2; mk <<= 1) {
                float ov = __shfl_xor_sync(0xffffffffu, v, mk);
                int om = __shfl_xor_sync(0xffffffffu, meta, mk);
                if (ov < v) { v = ov; meta = om; }
            }
            if ((lane & 3) == 0) {
                int row = cur_rb * 128 + wm * 32 + (s >> 1) * 16 + (s & 1) * 8 + (lane >> 2);
                atomicMin(&g_rowkey[row],
                          ((unsigned long long)fkey(v) << 32) | (unsigned)meta);
            }
        }
    }
}

// ---------------------------------------------------------------------------
// Tail: exact fp32 recompute over the 8 candidate columns of each row's
// winning group, then per-block sums.
// ---------------------------------------------------------------------------
__global__ __launch_bounds__(256)
void tail_kernel(const float* __restrict__ A, const float* __restrict__ B) {
    __shared__ float ws[8];
    const int tid = threadIdx.x;
    const int row = blockIdx.x * 256 + tid;
    const unsigned meta = (unsigned)(g_rowkey[row] & 0xFFFFFFFFull);
    const int base = (int)(meta >> 4) * 128 + ((meta >> 3) & 1) * 64 + (meta & 7);

    const float4* ar = reinterpret_cast<const float4*>(A) + (size_t)row * 16;
    float4 a4[16];
#pragma unroll
    for (int i = 0; i < 16; i++) a4[i] = ar[i];

    float best = 3.4e38f;
#pragma unroll
    for (int jj = 0; jj < 8; jj++) {
        const float4* br = reinterpret_cast<const float4*>(B) + (size_t)(base + jj * 8) * 16;
        float s = 0.f;
#pragma unroll
        for (int i = 0; i < 16; i++) {
            float4 b4 = br[i];
            float dx = a4[i].x - b4.x, dy = a4[i].y - b4.y;
            float dz = a4[i].z - b4.z, dw = a4[i].w - b4.w;
            s += dx * dx + dy * dy + dz * dz + dw * dw;
        }
        best = fminf(best, s);
    }
#pragma unroll
    for (int mk = 16; mk; mk >>= 1) best += __shfl_xor_sync(0xffffffffu, best, mk);
    if ((tid & 31) == 0) ws[tid >> 5] = best;
    __syncthreads();
    if (tid == 0) {
        float t = 0.f;
#pragma unroll
        for (int i = 0; i < 8; i++) t += ws[i];
        g_bsum[blockIdx.x] = t;
    }
}

// ---------------------------------------------------------------------------
__global__ void final_reduce_kernel(float* __restrict__ out) {
    int lane = threadIdx.x;
    float v = g_bsum[lane] + g_bsum[lane + 32];
#pragma unroll
    for (int mk = 16; mk; mk >>= 1) v += __shfl_xor_sync(0xffffffffu, v, mk);
    if (lane == 0) out[0] = v;
}

extern "C" void kernel_launch(void* const* d_in, const int* in_sizes, int n_in,
                              void* d_out, int out_size) {
    const float* A = (const float*)d_in[0];
    const float* B = (const float*)d_in[1];
    float* out = (float*)d_out;

    cudaFuncSetAttribute(dist_kernel, cudaFuncAttributeMaxDynamicSharedMemorySize, SMEM_BYTES);

    prep_kernel<<<2 * NRB, 256>>>(A, B);
    dist_kernel<<<NCTA, 256, SMEM_BYTES>>>();
    tail_kernel<<<NTAILB, 256>>>(A, B);
    final_reduce_kernel<<<1, 32>>>(out);
}